// round 13
// baseline (speedup 1.0000x reference)
#include <cuda_runtime.h>

#define NB   512
#define NT   1000
#define NC   64
#define NH   128
#define NTDA 150
#define NCLS 4

#define MT    128                // GEMM M-tile
#define NBLK  (NB * NT / MT)     // 4000 GEMM blocks

// Scratch (no cudaMalloc allowed)
__device__ float g_cur[(size_t)NB * NT * NH];   // currents [B*T, H]
__device__ float g_Wd[NC * NH];                 // W_fc^T   [k][n]
__device__ float g_Wt1T[NTDA * 64];             // Wt1^T    [c][o]
__device__ float g_Wt2T[64 * 64];               // Wt2^T    [c][o]
__device__ float g_Wc1T[(NH + 64) * NH];        // Wc1^T    [c][o]
__device__ float g_h[NB * NH];
__device__ float g_mean[NH];
__device__ float g_rstd[NH];

typedef unsigned long long u64;

__device__ __forceinline__ u64 fma2(u64 a, u64 b, u64 c) {
    u64 d;
    asm("fma.rn.f32x2 %0, %1, %2, %3;" : "=l"(d) : "l"(a), "l"(b), "l"(c));
    return d;
}
__device__ __forceinline__ u64 dup2(float v) {
    u64 d;
    asm("mov.b64 %0, {%1, %1};" : "=l"(d) : "f"(v));
    return d;
}
__device__ __forceinline__ void cp16(void* dst_smem, const void* src) {
    unsigned d = (unsigned)__cvta_generic_to_shared(dst_smem);
    asm volatile("cp.async.cg.shared.global [%0], [%1], 16;" :: "r"(d), "l"(src));
}

// ---------------------------------------------------------------------------
// Kernel 0: one-time weight transposes (weights tiny; runs in a few µs)
// ---------------------------------------------------------------------------
__global__ void __launch_bounds__(128) wtr_kernel(
    const float* __restrict__ Wfc, const float* __restrict__ Wt1,
    const float* __restrict__ Wt2, const float* __restrict__ Wc1)
{
    const int o = threadIdx.x;
#pragma unroll 8
    for (int k = 0; k < NC; k++) g_Wd[k * NH + o] = Wfc[o * NC + k];
    if (o < 64) {
        for (int c = 0; c < NTDA; c++) g_Wt1T[c * 64 + o] = Wt1[o * NTDA + c];
#pragma unroll 8
        for (int c = 0; c < 64; c++)   g_Wt2T[c * 64 + o] = Wt2[o * 64 + c];
    }
#pragma unroll 8
    for (int c = 0; c < NH + 64; c++) g_Wc1T[c * NH + o] = Wc1[o * (NH + 64) + c];
}

// ---------------------------------------------------------------------------
// Kernel 1: currents GEMM.  [MT x 128] tile per block, K=64 full.
// Thread (tm,tn): 8 M-rows x 8 N-cols (4 f32x2 pairs at n=4tn.. and 64+4tn..).
// Dense 64-float sx rows (16B-aligned; R11's 66-float padding misaligned the
// cp.async/float4 accesses and crashed).
// ---------------------------------------------------------------------------
__global__ void __launch_bounds__(256, 2) gemm_kernel(const float* __restrict__ x)
{
    __shared__ __align__(16) float sx[MT * NC];   // 32 KB
    __shared__ __align__(16) float sw[NC * NH];   // 32 KB

    const int tid = threadIdx.x;
    const size_t m0 = (size_t)blockIdx.x * MT;

    // Stage x tile (2048 float4) and W^T (2048 float4), both coalesced.
    const char* xsrc = (const char*)(x + m0 * NC);
#pragma unroll
    for (int r = 0; r < 8; r++) {
        int p = tid + (r << 8);
        cp16((char*)sx + p * 16, xsrc + p * 16);
    }
    const char* wsrc = (const char*)g_Wd;
#pragma unroll
    for (int r = 0; r < 8; r++) {
        int p = tid + (r << 8);
        cp16((char*)sw + p * 16, wsrc + p * 16);
    }
    asm volatile("cp.async.commit_group;");
    asm volatile("cp.async.wait_group 0;");
    __syncthreads();

    const int tm = tid >> 4, tn = tid & 15;
    const float* am = sx + tm * 8 * NC;

    u64 acc[8][4];
#pragma unroll
    for (int mi = 0; mi < 8; mi++)
#pragma unroll
        for (int j = 0; j < 4; j++) acc[mi][j] = 0ull;

    for (int k4 = 0; k4 < 16; k4++) {
        float4 a4[8];
#pragma unroll
        for (int mi = 0; mi < 8; mi++)
            a4[mi] = *(const float4*)(am + mi * NC + k4 * 4);
#pragma unroll
        for (int kk = 0; kk < 4; kk++) {
            const float* brow = sw + (k4 * 4 + kk) * NH + tn * 4;
            ulonglong2 b0 = *(const ulonglong2*)brow;          // n = 4tn..+3
            ulonglong2 b1 = *(const ulonglong2*)(brow + 64);   // n = 64+4tn..+3
#pragma unroll
            for (int mi = 0; mi < 8; mi++) {
                const float* af = (const float*)&a4[mi];
                u64 ad = dup2(af[kk]);
                acc[mi][0] = fma2(ad, b0.x, acc[mi][0]);
                acc[mi][1] = fma2(ad, b0.y, acc[mi][1]);
                acc[mi][2] = fma2(ad, b1.x, acc[mi][2]);
                acc[mi][3] = fma2(ad, b1.y, acc[mi][3]);
            }
        }
    }

    float* crow = g_cur + (m0 + tm * 8) * NH + tn * 4;
#pragma unroll
    for (int mi = 0; mi < 8; mi++) {
        ulonglong2 v0; v0.x = acc[mi][0]; v0.y = acc[mi][1];
        ulonglong2 v1; v1.x = acc[mi][2]; v1.y = acc[mi][3];
        *(ulonglong2*)(crow + mi * NH)      = v0;
        *(ulonglong2*)(crow + mi * NH + 64) = v1;
    }
}

// ---------------------------------------------------------------------------
// Kernel 2: LIF scan.  Warp = one batch; lane owns 4 consecutive h (float4
// loads over t, 4 independent LIF chains for ILP). Bias folded here.
// ---------------------------------------------------------------------------
__global__ void __launch_bounds__(128) scan_kernel(
    const float* __restrict__ bfc, float* __restrict__ counts_out)
{
    const int w = threadIdx.x >> 5, l = threadIdx.x & 31;
    const int b = blockIdx.x * 4 + w;
    const float4* cur = (const float4*)(g_cur + (size_t)b * NT * NH) + l;
    const float4 bias = ((const float4*)bfc)[l];

    float m0 = 0, m1 = 0, m2 = 0, m3 = 0;
    float c0 = 0, c1 = 0, c2 = 0, c3 = 0;

    for (int t = 0; t < NT; t += 4) {
        float4 v[4];
#pragma unroll
        for (int i = 0; i < 4; i++) v[i] = cur[(t + i) * (NH / 4)];
#pragma unroll
        for (int i = 0; i < 4; i++) {
            m0 = fmaf(m0, 0.9f, v[i].x + bias.x); if (m0 >= 1.0f) { c0 += 1.0f; m0 = 0.0f; }
            m1 = fmaf(m1, 0.9f, v[i].y + bias.y); if (m1 >= 1.0f) { c1 += 1.0f; m1 = 0.0f; }
            m2 = fmaf(m2, 0.9f, v[i].z + bias.z); if (m2 >= 1.0f) { c2 += 1.0f; m2 = 0.0f; }
            m3 = fmaf(m3, 0.9f, v[i].w + bias.w); if (m3 >= 1.0f) { c3 += 1.0f; m3 = 0.0f; }
        }
    }
    float4 r; r.x = c0; r.y = c1; r.z = c2; r.w = c3;
    ((float4*)(counts_out + b * NH))[l] = r;
}

// ---------------------------------------------------------------------------
// Kernel 3: tda MLP + classifier layer 1, coalesced via transposed weights.
// Thread tid = output feature; loads W^T[c][tid] consecutive across lanes.
// ---------------------------------------------------------------------------
__global__ void __launch_bounds__(128) head_kernel(
    const float* __restrict__ tda,
    const float* __restrict__ bt1, const float* __restrict__ bt2,
    const float* __restrict__ bc1, const float* __restrict__ counts)
{
    __shared__ float s_tda[NTDA];
    __shared__ float s_h1[64];
    __shared__ float s_f[NH + 64];   // [firing_rate(128) | tda_out(64)]

    const int b = blockIdx.x, tid = threadIdx.x;

    for (int i = tid; i < NTDA; i += 128) s_tda[i] = tda[b * NTDA + i];
    s_f[tid] = counts[b * NH + tid] * (1.0f / (float)NT);
    __syncthreads();

    if (tid < 64) {
        float a = bt1[tid];
#pragma unroll 5
        for (int c = 0; c < NTDA; c++) a = fmaf(g_Wt1T[c * 64 + tid], s_tda[c], a);
        s_h1[tid] = fmaxf(a, 0.0f);
    }
    __syncthreads();

    if (tid < 64) {
        float a = bt2[tid];
#pragma unroll 8
        for (int c = 0; c < 64; c++) a = fmaf(g_Wt2T[c * 64 + tid], s_h1[c], a);
        s_f[NH + tid] = fmaxf(a, 0.0f);
    }
    __syncthreads();

    float a = bc1[tid];
#pragma unroll 8
    for (int c = 0; c < NH + 64; c++) a = fmaf(g_Wc1T[c * NH + tid], s_f[c], a);
    g_h[b * NH + tid] = a;
}

// ---------------------------------------------------------------------------
// Kernel 4: BatchNorm batch statistics (two-pass, biased variance)
// ---------------------------------------------------------------------------
__global__ void __launch_bounds__(256) bn_stats_kernel()
{
    const int j = blockIdx.x, tid = threadIdx.x;
    __shared__ float red[256];
    __shared__ float m_sh;

    float v1 = g_h[tid * NH + j];
    float v2 = g_h[(tid + 256) * NH + j];

    red[tid] = v1 + v2;
    __syncthreads();
    for (int o = 128; o > 0; o >>= 1) {
        if (tid < o) red[tid] += red[tid + o];
        __syncthreads();
    }
    if (tid == 0) m_sh = red[0] * (1.0f / (float)NB);
    __syncthreads();

    const float m = m_sh;
    float d1 = v1 - m, d2 = v2 - m;
    red[tid] = d1 * d1 + d2 * d2;
    __syncthreads();
    for (int o = 128; o > 0; o >>= 1) {
        if (tid < o) red[tid] += red[tid + o];
        __syncthreads();
    }
    if (tid == 0) {
        g_mean[j] = m;
        g_rstd[j] = rsqrtf(red[0] * (1.0f / (float)NB) + 1e-5f);
    }
}

// ---------------------------------------------------------------------------
// Kernel 5: BN apply + ReLU + final Linear(128 -> 4)
// ---------------------------------------------------------------------------
__global__ void __launch_bounds__(128) out_kernel(
    const float* __restrict__ gamma, const float* __restrict__ beta,
    const float* __restrict__ Wc2, const float* __restrict__ bc2,
    float* __restrict__ out)
{
    __shared__ float sv[NH];
    const int b = blockIdx.x, tid = threadIdx.x;

    float v = (g_h[b * NH + tid] - g_mean[tid]) * g_rstd[tid] * gamma[tid] + beta[tid];
    sv[tid] = fmaxf(v, 0.0f);
    __syncthreads();

    const int w = tid >> 5, l = tid & 31;
    const float* wr = Wc2 + w * NH;
    float p = sv[l] * wr[l] + sv[l + 32] * wr[l + 32]
            + sv[l + 64] * wr[l + 64] + sv[l + 96] * wr[l + 96];
#pragma unroll
    for (int o = 16; o > 0; o >>= 1) p += __shfl_down_sync(0xffffffffu, p, o);
    if (l == 0) out[b * NCLS + w] = p + bc2[w];
}

// ---------------------------------------------------------------------------
extern "C" void kernel_launch(void* const* d_in, const int* in_sizes, int n_in,
                              void* d_out, int out_size)
{
    const float* x     = (const float*)d_in[0];   // [512,1000,64]
    const float* tda   = (const float*)d_in[1];   // [512,150]
    const float* Wfc   = (const float*)d_in[2];   // [128,64]
    const float* bfc   = (const float*)d_in[3];   // [128]
    const float* Wt1   = (const float*)d_in[4];   // [64,150]
    const float* bt1   = (const float*)d_in[5];   // [64]
    const float* Wt2   = (const float*)d_in[6];   // [64,64]
    const float* bt2   = (const float*)d_in[7];   // [64]
    const float* Wc1   = (const float*)d_in[8];   // [128,192]
    const float* bc1   = (const float*)d_in[9];   // [128]
    const float* gamma = (const float*)d_in[10];  // [128]
    const float* beta  = (const float*)d_in[11];  // [128]
    const float* Wc2   = (const float*)d_in[12];  // [4,128]
    const float* bc2   = (const float*)d_in[13];  // [4]

    float* out    = (float*)d_out;        // first 512*4 = logits
    float* counts = out + NB * NCLS;      // next 512*128 = spike_counts

    wtr_kernel<<<1, 128>>>(Wfc, Wt1, Wt2, Wc1);
    gemm_kernel<<<NBLK, 256>>>(x);
    scan_kernel<<<NB / 4, 128>>>(bfc, counts);
    head_kernel<<<NB, 128>>>(tda, bt1, bt2, bc1, counts);
    bn_stats_kernel<<<NH, 256>>>();
    out_kernel<<<NB, 128>>>(gamma, beta, Wc2, bc2, out);
}

// round 14
// speedup vs baseline: 1.6348x; 1.6348x over previous
#include <cuda_runtime.h>

#define NB   512
#define NT   1000
#define NC   64
#define NH   128
#define NTDA 150
#define NCLS 4

#define MT    128                // GEMM M-tile
#define NBLK  (NB * NT / MT)     // 4000 GEMM blocks

// Scratch (no cudaMalloc allowed)
__device__ float g_cur[(size_t)NB * NT * NH];   // currents [B*T, H]
__device__ float g_Wd[NC * NH];                 // W_fc^T   [k][n]
__device__ float g_Wt1T[NTDA * 64];             // Wt1^T    [c][o]
__device__ float g_Wt2T[64 * 64];               // Wt2^T    [c][o]
__device__ float g_Wc1T[(NH + 64) * NH];        // Wc1^T    [c][o]
__device__ float g_h[NB * NH];
__device__ float g_mean[NH];
__device__ float g_rstd[NH];

typedef unsigned long long u64;

__device__ __forceinline__ u64 fma2(u64 a, u64 b, u64 c) {
    u64 d;
    asm("fma.rn.f32x2 %0, %1, %2, %3;" : "=l"(d) : "l"(a), "l"(b), "l"(c));
    return d;
}
__device__ __forceinline__ u64 dup2(float v) {
    u64 d;
    asm("mov.b64 %0, {%1, %1};" : "=l"(d) : "f"(v));
    return d;
}
__device__ __forceinline__ void cp16(void* dst_smem, const void* src) {
    unsigned d = (unsigned)__cvta_generic_to_shared(dst_smem);
    asm volatile("cp.async.cg.shared.global [%0], [%1], 16;" :: "r"(d), "l"(src));
}

// ---------------------------------------------------------------------------
// Kernels 0a/0b/0c: one-time weight transposes, split into three launches so
// gemm_kernel sits at launch index 3 (the slot ncu empirically captures).
// ---------------------------------------------------------------------------
__global__ void __launch_bounds__(128) wtr_fc_kernel(const float* __restrict__ Wfc)
{
    const int o = threadIdx.x;
#pragma unroll 8
    for (int k = 0; k < NC; k++) g_Wd[k * NH + o] = Wfc[o * NC + k];
}
__global__ void __launch_bounds__(64) wtr_tda_kernel(
    const float* __restrict__ Wt1, const float* __restrict__ Wt2)
{
    const int o = threadIdx.x;
    for (int c = 0; c < NTDA; c++) g_Wt1T[c * 64 + o] = Wt1[o * NTDA + c];
#pragma unroll 8
    for (int c = 0; c < 64; c++)   g_Wt2T[c * 64 + o] = Wt2[o * 64 + c];
}
__global__ void __launch_bounds__(128) wtr_c1_kernel(const float* __restrict__ Wc1)
{
    const int o = threadIdx.x;
#pragma unroll 8
    for (int c = 0; c < NH + 64; c++) g_Wc1T[c * NH + o] = Wc1[o * (NH + 64) + c];
}

// ---------------------------------------------------------------------------
// Kernel 1: currents GEMM.  [MT x 128] tile per block, K=64 full.
// Thread (tm,tn): 8 M-rows x 8 N-cols (4 f32x2 pairs at n=4tn.. and 64+4tn..).
// ---------------------------------------------------------------------------
__global__ void __launch_bounds__(256, 2) gemm_kernel(const float* __restrict__ x)
{
    __shared__ __align__(16) float sx[MT * NC];   // 32 KB
    __shared__ __align__(16) float sw[NC * NH];   // 32 KB

    const int tid = threadIdx.x;
    const size_t m0 = (size_t)blockIdx.x * MT;

    // Stage x tile (2048 float4) and W^T (2048 float4), both coalesced.
    const char* xsrc = (const char*)(x + m0 * NC);
#pragma unroll
    for (int r = 0; r < 8; r++) {
        int p = tid + (r << 8);
        cp16((char*)sx + p * 16, xsrc + p * 16);
    }
    const char* wsrc = (const char*)g_Wd;
#pragma unroll
    for (int r = 0; r < 8; r++) {
        int p = tid + (r << 8);
        cp16((char*)sw + p * 16, wsrc + p * 16);
    }
    asm volatile("cp.async.commit_group;");
    asm volatile("cp.async.wait_group 0;");
    __syncthreads();

    const int tm = tid >> 4, tn = tid & 15;
    const float* am = sx + tm * 8 * NC;

    u64 acc[8][4];
#pragma unroll
    for (int mi = 0; mi < 8; mi++)
#pragma unroll
        for (int j = 0; j < 4; j++) acc[mi][j] = 0ull;

    for (int k4 = 0; k4 < 16; k4++) {
        float4 a4[8];
#pragma unroll
        for (int mi = 0; mi < 8; mi++)
            a4[mi] = *(const float4*)(am + mi * NC + k4 * 4);
#pragma unroll
        for (int kk = 0; kk < 4; kk++) {
            const float* brow = sw + (k4 * 4 + kk) * NH + tn * 4;
            ulonglong2 b0 = *(const ulonglong2*)brow;          // n = 4tn..+3
            ulonglong2 b1 = *(const ulonglong2*)(brow + 64);   // n = 64+4tn..+3
#pragma unroll
            for (int mi = 0; mi < 8; mi++) {
                const float* af = (const float*)&a4[mi];
                u64 ad = dup2(af[kk]);
                acc[mi][0] = fma2(ad, b0.x, acc[mi][0]);
                acc[mi][1] = fma2(ad, b0.y, acc[mi][1]);
                acc[mi][2] = fma2(ad, b1.x, acc[mi][2]);
                acc[mi][3] = fma2(ad, b1.y, acc[mi][3]);
            }
        }
    }

    float* crow = g_cur + (m0 + tm * 8) * NH + tn * 4;
#pragma unroll
    for (int mi = 0; mi < 8; mi++) {
        ulonglong2 v0; v0.x = acc[mi][0]; v0.y = acc[mi][1];
        ulonglong2 v1; v1.x = acc[mi][2]; v1.y = acc[mi][3];
        *(ulonglong2*)(crow + mi * NH)      = v0;
        *(ulonglong2*)(crow + mi * NH + 64) = v1;
    }
}

// ---------------------------------------------------------------------------
// Kernel 2: LIF scan (R10 shape: 2048 warps for latency hiding).
// Thread = (b,h); coalesced scalar LDG over t, unroll 8; bias folded here.
// ---------------------------------------------------------------------------
__global__ void __launch_bounds__(128) scan_kernel(
    const float* __restrict__ bfc, float* __restrict__ counts_out)
{
    const int b = blockIdx.x, h = threadIdx.x;
    const float* cur = g_cur + (size_t)b * NT * NH + h;
    const float bias = bfc[h];

    float mem = 0.0f, cnt = 0.0f;
    for (int tg = 0; tg < NT / 8; tg++) {
        float c[8];
#pragma unroll
        for (int i = 0; i < 8; i++) c[i] = cur[(tg * 8 + i) * NH];
#pragma unroll
        for (int i = 0; i < 8; i++) {
            mem = fmaf(mem, 0.9f, c[i] + bias);
            if (mem >= 1.0f) { cnt += 1.0f; mem = 0.0f; }
        }
    }
    counts_out[b * NH + h] = cnt;
}

// ---------------------------------------------------------------------------
// Kernel 3: tda MLP + classifier layer 1, coalesced via transposed weights.
// ---------------------------------------------------------------------------
__global__ void __launch_bounds__(128) head_kernel(
    const float* __restrict__ tda,
    const float* __restrict__ bt1, const float* __restrict__ bt2,
    const float* __restrict__ bc1, const float* __restrict__ counts)
{
    __shared__ float s_tda[NTDA];
    __shared__ float s_h1[64];
    __shared__ float s_f[NH + 64];   // [firing_rate(128) | tda_out(64)]

    const int b = blockIdx.x, tid = threadIdx.x;

    for (int i = tid; i < NTDA; i += 128) s_tda[i] = tda[b * NTDA + i];
    s_f[tid] = counts[b * NH + tid] * (1.0f / (float)NT);
    __syncthreads();

    if (tid < 64) {
        float a = bt1[tid];
#pragma unroll 5
        for (int c = 0; c < NTDA; c++) a = fmaf(g_Wt1T[c * 64 + tid], s_tda[c], a);
        s_h1[tid] = fmaxf(a, 0.0f);
    }
    __syncthreads();

    if (tid < 64) {
        float a = bt2[tid];
#pragma unroll 8
        for (int c = 0; c < 64; c++) a = fmaf(g_Wt2T[c * 64 + tid], s_h1[c], a);
        s_f[NH + tid] = fmaxf(a, 0.0f);
    }
    __syncthreads();

    float a = bc1[tid];
#pragma unroll 8
    for (int c = 0; c < NH + 64; c++) a = fmaf(g_Wc1T[c * NH + tid], s_f[c], a);
    g_h[b * NH + tid] = a;
}

// ---------------------------------------------------------------------------
// Kernel 4: BatchNorm batch statistics (two-pass, biased variance)
// ---------------------------------------------------------------------------
__global__ void __launch_bounds__(256) bn_stats_kernel()
{
    const int j = blockIdx.x, tid = threadIdx.x;
    __shared__ float red[256];
    __shared__ float m_sh;

    float v1 = g_h[tid * NH + j];
    float v2 = g_h[(tid + 256) * NH + j];

    red[tid] = v1 + v2;
    __syncthreads();
    for (int o = 128; o > 0; o >>= 1) {
        if (tid < o) red[tid] += red[tid + o];
        __syncthreads();
    }
    if (tid == 0) m_sh = red[0] * (1.0f / (float)NB);
    __syncthreads();

    const float m = m_sh;
    float d1 = v1 - m, d2 = v2 - m;
    red[tid] = d1 * d1 + d2 * d2;
    __syncthreads();
    for (int o = 128; o > 0; o >>= 1) {
        if (tid < o) red[tid] += red[tid + o];
        __syncthreads();
    }
    if (tid == 0) {
        g_mean[j] = m;
        g_rstd[j] = rsqrtf(red[0] * (1.0f / (float)NB) + 1e-5f);
    }
}

// ---------------------------------------------------------------------------
// Kernel 5: BN apply + ReLU + final Linear(128 -> 4)
// ---------------------------------------------------------------------------
__global__ void __launch_bounds__(128) out_kernel(
    const float* __restrict__ gamma, const float* __restrict__ beta,
    const float* __restrict__ Wc2, const float* __restrict__ bc2,
    float* __restrict__ out)
{
    __shared__ float sv[NH];
    const int b = blockIdx.x, tid = threadIdx.x;

    float v = (g_h[b * NH + tid] - g_mean[tid]) * g_rstd[tid] * gamma[tid] + beta[tid];
    sv[tid] = fmaxf(v, 0.0f);
    __syncthreads();

    const int w = tid >> 5, l = tid & 31;
    const float* wr = Wc2 + w * NH;
    float p = sv[l] * wr[l] + sv[l + 32] * wr[l + 32]
            + sv[l + 64] * wr[l + 64] + sv[l + 96] * wr[l + 96];
#pragma unroll
    for (int o = 16; o > 0; o >>= 1) p += __shfl_down_sync(0xffffffffu, p, o);
    if (l == 0) out[b * NCLS + w] = p + bc2[w];
}

// ---------------------------------------------------------------------------
extern "C" void kernel_launch(void* const* d_in, const int* in_sizes, int n_in,
                              void* d_out, int out_size)
{
    const float* x     = (const float*)d_in[0];   // [512,1000,64]
    const float* tda   = (const float*)d_in[1];   // [512,150]
    const float* Wfc   = (const float*)d_in[2];   // [128,64]
    const float* bfc   = (const float*)d_in[3];   // [128]
    const float* Wt1   = (const float*)d_in[4];   // [64,150]
    const float* bt1   = (const float*)d_in[5];   // [64]
    const float* Wt2   = (const float*)d_in[6];   // [64,64]
    const float* bt2   = (const float*)d_in[7];   // [64]
    const float* Wc1   = (const float*)d_in[8];   // [128,192]
    const float* bc1   = (const float*)d_in[9];   // [128]
    const float* gamma = (const float*)d_in[10];  // [128]
    const float* beta  = (const float*)d_in[11];  // [128]
    const float* Wc2   = (const float*)d_in[12];  // [4,128]
    const float* bc2   = (const float*)d_in[13];  // [4]

    float* out    = (float*)d_out;        // first 512*4 = logits
    float* counts = out + NB * NCLS;      // next 512*128 = spike_counts

    wtr_fc_kernel<<<1, 128>>>(Wfc);                 // launch 0
    wtr_tda_kernel<<<1, 64>>>(Wt1, Wt2);            // launch 1
    wtr_c1_kernel<<<1, 128>>>(Wc1);                 // launch 2
    gemm_kernel<<<NBLK, 256>>>(x);                  // launch 3  <- ncu slot
    scan_kernel<<<NB, 128>>>(bfc, counts);          // launch 4
    head_kernel<<<NB, 128>>>(tda, bt1, bt2, bc1, counts);
    bn_stats_kernel<<<NH, 256>>>();
    out_kernel<<<NB, 128>>>(gamma, beta, Wc2, bc2, out);
}

// round 17
// speedup vs baseline: 2.0507x; 1.2544x over previous
#include <cuda_runtime.h>
#include <cuda_bf16.h>
#include <cstdint>

#define NB   512
#define NT   1000
#define NC   64
#define NH   128
#define NTDA 150
#define NCLS 4

#define MT    128
#define NBLK  (NB * NT / MT)     // 4000 tiles

// Dynamic smem: bf16 tiles, rows padded to 144 B (ldmatrix conflict-free)
#define ROWB    144
#define SM_AHI  0
#define SM_ALO  18432
#define SM_BHI  36864
#define SM_BLO  55296
#define SMEM_DYN 73728

// Scratch (no cudaMalloc allowed)
__device__ float g_cur[(size_t)NB * NT * NH];   // currents [B*T, H]
__device__ __nv_bfloat16 g_Whi[NH * NC];        // W_fc hi [n][k]
__device__ __nv_bfloat16 g_Wlo[NH * NC];        // W_fc lo [n][k]
__device__ float g_Wt1T[NTDA * 64];
__device__ float g_Wt2T[64 * 64];
__device__ float g_Wc1T[(NH + 64) * NH];
__device__ float g_h[NB * NH];
__device__ float g_mean[NH];
__device__ float g_rstd[NH];

__device__ __forceinline__ uint32_t smem_u32(const void* p) {
    return (uint32_t)__cvta_generic_to_shared(p);
}
__device__ __forceinline__ void cp16(void* dst_smem, const void* src) {
    unsigned d = (unsigned)__cvta_generic_to_shared(dst_smem);
    asm volatile("cp.async.cg.shared.global [%0], [%1], 16;" :: "r"(d), "l"(src));
}
__device__ __forceinline__ void ldm4(uint32_t* r, uint32_t addr) {
    asm volatile("ldmatrix.sync.aligned.m8n8.x4.shared.b16 {%0,%1,%2,%3}, [%4];"
        : "=r"(r[0]), "=r"(r[1]), "=r"(r[2]), "=r"(r[3]) : "r"(addr));
}
__device__ __forceinline__ void mma16816(float* d, const uint32_t* a, const uint32_t* b) {
    asm volatile(
        "mma.sync.aligned.m16n8k16.row.col.f32.bf16.bf16.f32 "
        "{%0,%1,%2,%3}, {%4,%5,%6,%7}, {%8,%9}, {%0,%1,%2,%3};"
        : "+f"(d[0]), "+f"(d[1]), "+f"(d[2]), "+f"(d[3])
        : "r"(a[0]), "r"(a[1]), "r"(a[2]), "r"(a[3]), "r"(b[0]), "r"(b[1]));
}

// ---------------------------------------------------------------------------
// Kernels 0a/0b/0c: one-time weight prep (gemm stays launch 3 = ncu slot)
// ---------------------------------------------------------------------------
__global__ void __launch_bounds__(128) wtr_fc_kernel(const float* __restrict__ Wfc)
{
    const int o = threadIdx.x;
#pragma unroll 8
    for (int k = 0; k < NC; k++) {
        float w = Wfc[o * NC + k];
        __nv_bfloat16 h = __float2bfloat16(w);
        g_Whi[o * NC + k] = h;
        g_Wlo[o * NC + k] = __float2bfloat16(w - __bfloat162float(h));
    }
}
__global__ void __launch_bounds__(64) wtr_tda_kernel(
    const float* __restrict__ Wt1, const float* __restrict__ Wt2)
{
    const int o = threadIdx.x;
    for (int c = 0; c < NTDA; c++) g_Wt1T[c * 64 + o] = Wt1[o * NTDA + c];
#pragma unroll 8
    for (int c = 0; c < 64; c++)   g_Wt2T[c * 64 + o] = Wt2[o * 64 + c];
}
__global__ void __launch_bounds__(128) wtr_c1_kernel(const float* __restrict__ Wc1)
{
    const int o = threadIdx.x;
#pragma unroll 8
    for (int c = 0; c < NH + 64; c++) g_Wc1T[c * NH + o] = Wc1[o * (NH + 64) + c];
}

// ---------------------------------------------------------------------------
// Kernel 1: currents GEMM via mma.sync (bf16 3-term split, fp32 acc).
// Tile [128m x 128n], K=64. 8 warps: wm = w&1 (64 m-rows), wn = w>>1 (32 n).
// Warp: 4 m16-frags x 4 n8-frags, k in 4 chunks of 16.
// ---------------------------------------------------------------------------
__global__ void __launch_bounds__(256, 2) gemm_kernel(const float* __restrict__ x)
{
    extern __shared__ __align__(16) unsigned char sm[];
    const int tid = threadIdx.x;
    const int wid = tid >> 5, lane = tid & 31;
    const size_t m0 = (size_t)blockIdx.x * MT;
    const uint32_t sbase = smem_u32(sm);

    // Stage B hi/lo: 128 n-rows x 128B each -> padded 144B rows (cp.async)
#pragma unroll
    for (int r = 0; r < 4; r++) {
        int p = tid + (r << 8);            // 0..1023 16B pieces
        int n = p >> 3, piece = p & 7;
        cp16(sm + SM_BHI + n * ROWB + piece * 16, (const char*)g_Whi + p * 16);
        cp16(sm + SM_BLO + n * ROWB + piece * 16, (const char*)g_Wlo + p * 16);
    }
    asm volatile("cp.async.commit_group;");

    // Stage A: LDG fp32 x tile, split into bf16 hi/lo, STS into padded rows
    const float4* xsrc = (const float4*)(x + m0 * NC);
#pragma unroll
    for (int r = 0; r < 8; r++) {
        int idx = tid + (r << 8);          // 0..2047 float4s
        int m = idx >> 4, k4 = idx & 15;
        float4 v = xsrc[idx];
        __nv_bfloat162 h01 = __floats2bfloat162_rn(v.x, v.y);
        __nv_bfloat162 h23 = __floats2bfloat162_rn(v.z, v.w);
        float l0 = v.x - __bfloat162float(h01.x);
        float l1 = v.y - __bfloat162float(h01.y);
        float l2 = v.z - __bfloat162float(h23.x);
        float l3 = v.w - __bfloat162float(h23.y);
        __nv_bfloat162 q01 = __floats2bfloat162_rn(l0, l1);
        __nv_bfloat162 q23 = __floats2bfloat162_rn(l2, l3);
        uint32_t off = (uint32_t)(m * ROWB + k4 * 8);
        *(uint2*)(sm + SM_AHI + off) = make_uint2(*(uint32_t*)&h01, *(uint32_t*)&h23);
        *(uint2*)(sm + SM_ALO + off) = make_uint2(*(uint32_t*)&q01, *(uint32_t*)&q23);
    }
    asm volatile("cp.async.wait_group 0;");
    __syncthreads();

    const int wm = wid & 1, wn = wid >> 1;

    // ldmatrix lane-address bases (within a 128-row tile, rows padded ROWB)
    // A x4: matrices {m0..7,k0..7},{m8..15,k0..7},{m0..7,k8..15},{m8..15,k8..15}
    const uint32_t aBase = sbase + (uint32_t)((lane & 15) * ROWB)
                         + ((lane & 16) ? 16u : 0u)
                         + (uint32_t)(wm * 64 * ROWB);
    // B x4: matrices {n0..7,k0..7},{n0..7,k8..15},{n8..15,k0..7},{n8..15,k8..15}
    const uint32_t bBase = sbase + (uint32_t)((((lane & 7) + ((lane >> 1) & 8)) * ROWB))
                         + ((lane & 8) ? 16u : 0u)
                         + (uint32_t)(wn * 32 * ROWB);

    float acc[4][4][4];
#pragma unroll
    for (int mi = 0; mi < 4; mi++)
#pragma unroll
        for (int ni = 0; ni < 4; ni++)
#pragma unroll
            for (int q = 0; q < 4; q++) acc[mi][ni][q] = 0.0f;

#pragma unroll
    for (int kc = 0; kc < 4; kc++) {
        const uint32_t k2 = kc * 32;       // k0 * 2 bytes
        uint32_t ah[4][4], al[4][4], bh[4][2], bl[4][2];
        {
            uint32_t r[4];
            ldm4(r, bBase + SM_BHI + k2);
            bh[0][0] = r[0]; bh[0][1] = r[1]; bh[1][0] = r[2]; bh[1][1] = r[3];
            ldm4(r, bBase + SM_BHI + 16 * ROWB + k2);
            bh[2][0] = r[0]; bh[2][1] = r[1]; bh[3][0] = r[2]; bh[3][1] = r[3];
            ldm4(r, bBase + SM_BLO + k2);
            bl[0][0] = r[0]; bl[0][1] = r[1]; bl[1][0] = r[2]; bl[1][1] = r[3];
            ldm4(r, bBase + SM_BLO + 16 * ROWB + k2);
            bl[2][0] = r[0]; bl[2][1] = r[1]; bl[3][0] = r[2]; bl[3][1] = r[3];
        }
#pragma unroll
        for (int mi = 0; mi < 4; mi++) {
            ldm4(ah[mi], aBase + SM_AHI + (uint32_t)(mi * 16 * ROWB) + k2);
            ldm4(al[mi], aBase + SM_ALO + (uint32_t)(mi * 16 * ROWB) + k2);
        }
#pragma unroll
        for (int mi = 0; mi < 4; mi++)
#pragma unroll
            for (int ni = 0; ni < 4; ni++) {
                mma16816(acc[mi][ni], ah[mi], bh[ni]);   // hi*hi
                mma16816(acc[mi][ni], ah[mi], bl[ni]);   // hi*lo
                mma16816(acc[mi][ni], al[mi], bh[ni]);   // lo*hi
            }
    }

    // Epilogue: fragment regs -> g_cur (float2 stores)
    const int gid = lane >> 2, tig = lane & 3;
#pragma unroll
    for (int mi = 0; mi < 4; mi++) {
        size_t row = m0 + (size_t)(wm * 64 + mi * 16 + gid);
#pragma unroll
        for (int ni = 0; ni < 4; ni++) {
            int col = wn * 32 + ni * 8 + 2 * tig;
            float2 v01; v01.x = acc[mi][ni][0]; v01.y = acc[mi][ni][1];
            float2 v23; v23.x = acc[mi][ni][2]; v23.y = acc[mi][ni][3];
            *(float2*)(g_cur + row * NH + col)       = v01;
            *(float2*)(g_cur + (row + 8) * NH + col) = v23;
        }
    }
}

// ---------------------------------------------------------------------------
// Kernel 2: LIF scan. Thread=(b,h); coalesced LDG over t, unroll 16 (MLP 16).
// ---------------------------------------------------------------------------
__global__ void __launch_bounds__(128) scan_kernel(
    const float* __restrict__ bfc, float* __restrict__ counts_out)
{
    const int b = blockIdx.x, h = threadIdx.x;
    const float* cur = g_cur + (size_t)b * NT * NH + h;
    const float bias = bfc[h];

    float mem = 0.0f, cnt = 0.0f;
    for (int tg = 0; tg < 62; tg++) {            // 62*16 = 992
        float c[16];
#pragma unroll
        for (int i = 0; i < 16; i++) c[i] = cur[(tg * 16 + i) * NH];
#pragma unroll
        for (int i = 0; i < 16; i++) {
            mem = fmaf(mem, 0.9f, c[i] + bias);
            if (mem >= 1.0f) { cnt += 1.0f; mem = 0.0f; }
        }
    }
    {
        float c[8];
#pragma unroll
        for (int i = 0; i < 8; i++) c[i] = cur[(992 + i) * NH];
#pragma unroll
        for (int i = 0; i < 8; i++) {
            mem = fmaf(mem, 0.9f, c[i] + bias);
            if (mem >= 1.0f) { cnt += 1.0f; mem = 0.0f; }
        }
    }
    counts_out[b * NH + h] = cnt;
}

// ---------------------------------------------------------------------------
// Kernel 3: tda MLP + classifier layer 1. Coalesced weights + 4-way acc ILP.
// ---------------------------------------------------------------------------
__global__ void __launch_bounds__(128) head_kernel(
    const float* __restrict__ tda,
    const float* __restrict__ bt1, const float* __restrict__ bt2,
    const float* __restrict__ bc1, const float* __restrict__ counts)
{
    __shared__ float s_tda[NTDA];
    __shared__ float s_h1[64];
    __shared__ float s_f[NH + 64];

    const int b = blockIdx.x, tid = threadIdx.x;

    for (int i = tid; i < NTDA; i += 128) s_tda[i] = tda[b * NTDA + i];
    s_f[tid] = counts[b * NH + tid] * (1.0f / (float)NT);
    __syncthreads();

    if (tid < 64) {
        float a0 = bt1[tid], a1 = 0, a2 = 0, a3 = 0;
        int c = 0;
#pragma unroll 4
        for (; c + 3 < NTDA; c += 4) {
            a0 = fmaf(g_Wt1T[(c    ) * 64 + tid], s_tda[c    ], a0);
            a1 = fmaf(g_Wt1T[(c + 1) * 64 + tid], s_tda[c + 1], a1);
            a2 = fmaf(g_Wt1T[(c + 2) * 64 + tid], s_tda[c + 2], a2);
            a3 = fmaf(g_Wt1T[(c + 3) * 64 + tid], s_tda[c + 3], a3);
        }
        for (; c < NTDA; c++) a0 = fmaf(g_Wt1T[c * 64 + tid], s_tda[c], a0);
        s_h1[tid] = fmaxf((a0 + a1) + (a2 + a3), 0.0f);
    }
    __syncthreads();

    if (tid < 64) {
        float a0 = bt2[tid], a1 = 0, a2 = 0, a3 = 0;
#pragma unroll 4
        for (int c = 0; c < 64; c += 4) {
            a0 = fmaf(g_Wt2T[(c    ) * 64 + tid], s_h1[c    ], a0);
            a1 = fmaf(g_Wt2T[(c + 1) * 64 + tid], s_h1[c + 1], a1);
            a2 = fmaf(g_Wt2T[(c + 2) * 64 + tid], s_h1[c + 2], a2);
            a3 = fmaf(g_Wt2T[(c + 3) * 64 + tid], s_h1[c + 3], a3);
        }
        s_f[NH + tid] = fmaxf((a0 + a1) + (a2 + a3), 0.0f);
    }
    __syncthreads();

    float a0 = bc1[tid], a1 = 0, a2 = 0, a3 = 0;
#pragma unroll 4
    for (int c = 0; c < NH + 64; c += 4) {
        a0 = fmaf(g_Wc1T[(c    ) * NH + tid], s_f[c    ], a0);
        a1 = fmaf(g_Wc1T[(c + 1) * NH + tid], s_f[c + 1], a1);
        a2 = fmaf(g_Wc1T[(c + 2) * NH + tid], s_f[c + 2], a2);
        a3 = fmaf(g_Wc1T[(c + 3) * NH + tid], s_f[c + 3], a3);
    }
    g_h[b * NH + tid] = (a0 + a1) + (a2 + a3);
}

// ---------------------------------------------------------------------------
// Kernel 4: BatchNorm batch statistics (two-pass, biased variance)
// ---------------------------------------------------------------------------
__global__ void __launch_bounds__(256) bn_stats_kernel()
{
    const int j = blockIdx.x, tid = threadIdx.x;
    __shared__ float red[256];
    __shared__ float m_sh;

    float v1 = g_h[tid * NH + j];
    float v2 = g_h[(tid + 256) * NH + j];

    red[tid] = v1 + v2;
    __syncthreads();
    for (int o = 128; o > 0; o >>= 1) {
        if (tid < o) red[tid] += red[tid + o];
        __syncthreads();
    }
    if (tid == 0) m_sh = red[0] * (1.0f / (float)NB);
    __syncthreads();

    const float m = m_sh;
    float d1 = v1 - m, d2 = v2 - m;
    red[tid] = d1 * d1 + d2 * d2;
    __syncthreads();
    for (int o = 128; o > 0; o >>= 1) {
        if (tid < o) red[tid] += red[tid + o];
        __syncthreads();
    }
    if (tid == 0) {
        g_mean[j] = m;
        g_rstd[j] = rsqrtf(red[0] * (1.0f / (float)NB) + 1e-5f);
    }
}

// ---------------------------------------------------------------------------
// Kernel 5: BN apply + ReLU + final Linear(128 -> 4)
// ---------------------------------------------------------------------------
__global__ void __launch_bounds__(128) out_kernel(
    const float* __restrict__ gamma, const float* __restrict__ beta,
    const float* __restrict__ Wc2, const float* __restrict__ bc2,
    float* __restrict__ out)
{
    __shared__ float sv[NH];
    const int b = blockIdx.x, tid = threadIdx.x;

    float v = (g_h[b * NH + tid] - g_mean[tid]) * g_rstd[tid] * gamma[tid] + beta[tid];
    sv[tid] = fmaxf(v, 0.0f);
    __syncthreads();

    const int w = tid >> 5, l = tid & 31;
    const float* wr = Wc2 + w * NH;
    float p = sv[l] * wr[l] + sv[l + 32] * wr[l + 32]
            + sv[l + 64] * wr[l + 64] + sv[l + 96] * wr[l + 96];
#pragma unroll
    for (int o = 16; o > 0; o >>= 1) p += __shfl_down_sync(0xffffffffu, p, o);
    if (l == 0) out[b * NCLS + w] = p + bc2[w];
}

// ---------------------------------------------------------------------------
extern "C" void kernel_launch(void* const* d_in, const int* in_sizes, int n_in,
                              void* d_out, int out_size)
{
    const float* x     = (const float*)d_in[0];
    const float* tda   = (const float*)d_in[1];
    const float* Wfc   = (const float*)d_in[2];
    const float* bfc   = (const float*)d_in[3];
    const float* Wt1   = (const float*)d_in[4];
    const float* bt1   = (const float*)d_in[5];
    const float* Wt2   = (const float*)d_in[6];
    const float* bt2   = (const float*)d_in[7];
    const float* Wc1   = (const float*)d_in[8];
    const float* bc1   = (const float*)d_in[9];
    const float* gamma = (const float*)d_in[10];
    const float* beta  = (const float*)d_in[11];
    const float* Wc2   = (const float*)d_in[12];
    const float* bc2   = (const float*)d_in[13];

    float* out    = (float*)d_out;        // first 512*4 = logits
    float* counts = out + NB * NCLS;      // next 512*128 = spike_counts

    cudaFuncSetAttribute(gemm_kernel,
                         cudaFuncAttributeMaxDynamicSharedMemorySize, SMEM_DYN);

    wtr_fc_kernel<<<1, 128>>>(Wfc);                 // launch 0
    wtr_tda_kernel<<<1, 64>>>(Wt1, Wt2);            // launch 1
    wtr_c1_kernel<<<1, 128>>>(Wc1);                 // launch 2
    gemm_kernel<<<NBLK, 256, SMEM_DYN>>>(x);        // launch 3  <- ncu slot
    scan_kernel<<<NB, 128>>>(bfc, counts);          // launch 4
    head_kernel<<<NB, 128>>>(tda, bt1, bt2, bc1, counts);
    bn_stats_kernel<<<NH, 256>>>();
    out_kernel<<<NB, 128>>>(gamma, beta, Wc2, bc2, out);
}